// round 1
// baseline (speedup 1.0000x reference)
#include <cuda_runtime.h>
#include <cuda_bf16.h>

// ---------------------------------------------------------------------------
// Hetero-GNN (5 hetero_conv layers) over N=100000 nodes.
//   inter relation: 3.2M edges, MEAN aggregation
//   temp  relation: 100k edges, SUM aggregation
// Strategy: per-call CSR build (dst-indexed), transform-then-gather.
// All feature arrays fit in L2 (25.6MB each) -> gather is L2-bound, not HBM.
// ---------------------------------------------------------------------------

#define N_NODES 100000
#define MAXC 64

// Scratch (device globals; no allocation allowed)
__device__ float g_xt  [N_NODES * MAXC];
__device__ float g_xi  [N_NODES * MAXC];
__device__ float g_base[N_NODES * MAXC];
__device__ float g_proj[N_NODES * MAXC];
__device__ float g_h   [N_NODES * MAXC];
__device__ float g_h2  [N_NODES * MAXC];

__device__ int g_deg_t[N_NODES];        // degree, then reused as fill cursor
__device__ int g_deg_i[N_NODES];
__device__ int g_rpt  [N_NODES + 1];    // CSR row pointers (temp)
__device__ int g_rpi  [N_NODES + 1];    // CSR row pointers (inter)
__device__ int g_col_t[100000];
__device__ int g_col_i[3200000];

// ---------------------------------------------------------------------------
// CSR build kernels
// ---------------------------------------------------------------------------
__global__ void zero2_kernel(int* __restrict__ a, int* __restrict__ b, int n) {
    int i = blockIdx.x * blockDim.x + threadIdx.x;
    if (i < n) { a[i] = 0; b[i] = 0; }
}

__global__ void count_kernel(const int* __restrict__ dst, int E, int* __restrict__ deg) {
    int i = blockIdx.x * blockDim.x + threadIdx.x;
    if (i < E) atomicAdd(&deg[dst[i]], 1);
}

// Single-block exclusive scan over n entries. Writes rowptr[0..n] and turns
// deg[] into the fill cursor (cursor[i] = rowptr[i]).
__global__ void scan_kernel(int* __restrict__ deg, int* __restrict__ rowptr, int n) {
    __shared__ int sums[1024];
    int tid = threadIdx.x;
    int chunk = (n + 1023) / 1024;
    int st = tid * chunk;
    int en = st + chunk; if (en > n) en = n;
    int s = 0;
    for (int i = st; i < en; i++) s += deg[i];
    sums[tid] = s;
    __syncthreads();
    // inclusive Hillis-Steele scan
    for (int off = 1; off < 1024; off <<= 1) {
        int v = (tid >= off) ? sums[tid - off] : 0;
        __syncthreads();
        sums[tid] += v;
        __syncthreads();
    }
    int run = (tid > 0) ? sums[tid - 1] : 0;
    for (int i = st; i < en; i++) {
        int d = deg[i];
        rowptr[i] = run;
        deg[i]    = run;   // cursor for fill pass
        run += d;
    }
    if (tid == 1023) rowptr[n] = sums[1023];
}

__global__ void fill_kernel(const int* __restrict__ src, const int* __restrict__ dst,
                            int E, int* __restrict__ cursor, int* __restrict__ col) {
    int i = blockIdx.x * blockDim.x + threadIdx.x;
    if (i < E) {
        int d = dst[i];
        int p = atomicAdd(&cursor[d], 1);
        col[p] = src[i];
    }
}

// ---------------------------------------------------------------------------
// Transform: xt = x@Wt, xi = x@Wi, base = x@Wr + b [, proj = x@Wp]
// warp-per-node; lanes own output channels -> coalesced stores.
// ---------------------------------------------------------------------------
template<int CIN, int COUT, bool PROJ>
__global__ void transform_kernel(const float* __restrict__ x,
                                 const float* __restrict__ Wt,
                                 const float* __restrict__ Wi,
                                 const float* __restrict__ Wr,
                                 const float* __restrict__ b,
                                 const float* __restrict__ Wp,
                                 float* __restrict__ xt,
                                 float* __restrict__ xi,
                                 float* __restrict__ base,
                                 float* __restrict__ proj,
                                 int n) {
    __shared__ float sWt[CIN * COUT];
    __shared__ float sWi[CIN * COUT];
    __shared__ float sWr[CIN * COUT];
    __shared__ float sWp[PROJ ? (CIN * COUT) : 1];
    __shared__ float sB[COUT];
    for (int i = threadIdx.x; i < CIN * COUT; i += blockDim.x) {
        sWt[i] = Wt[i]; sWi[i] = Wi[i]; sWr[i] = Wr[i];
        if (PROJ) sWp[i] = Wp[i];
    }
    for (int i = threadIdx.x; i < COUT; i += blockDim.x) sB[i] = b[i];
    __syncthreads();

    int wpb  = blockDim.x >> 5;
    int node = blockIdx.x * wpb + (threadIdx.x >> 5);
    if (node >= n) return;
    int lane = threadIdx.x & 31;

    float xr[CIN];
#pragma unroll
    for (int ci = 0; ci < CIN; ci++) xr[ci] = x[node * CIN + ci];

    constexpr int R = (COUT + 31) / 32;
#pragma unroll
    for (int r = 0; r < R; r++) {
        int co = lane + 32 * r;
        float at = 0.f, ai = 0.f, ar = sB[co], ap = 0.f;
#pragma unroll
        for (int ci = 0; ci < CIN; ci++) {
            float xv = xr[ci];
            at = fmaf(xv, sWt[ci * COUT + co], at);
            ai = fmaf(xv, sWi[ci * COUT + co], ai);
            ar = fmaf(xv, sWr[ci * COUT + co], ar);
            if (PROJ) ap = fmaf(xv, sWp[ci * COUT + co], ap);
        }
        xt[node * COUT + co]   = at;
        xi[node * COUT + co]   = ai;
        base[node * COUT + co] = ar;
        if (PROJ) proj[node * COUT + co] = ap;
    }
}

// ---------------------------------------------------------------------------
// Aggregation, C=32. warp-per-node, lane = channel.
// MODE 0: out = relu(agg)            (head)
// MODE 1: out = relu(agg) + extra    (residual blocks, extra = h_prev)
// ---------------------------------------------------------------------------
template<int MODE>
__global__ void agg32_kernel(const float* __restrict__ xt, const float* __restrict__ xi,
                             const float* __restrict__ base,
                             const int* __restrict__ rpt, const int* __restrict__ colt,
                             const int* __restrict__ rpi, const int* __restrict__ coli,
                             const float* __restrict__ extra,
                             float* __restrict__ out, int n) {
    int node = blockIdx.x * (blockDim.x >> 5) + (threadIdx.x >> 5);
    if (node >= n) return;
    int lane = threadIdx.x & 31;

    float st = 0.f, si = 0.f;

    int b0 = rpt[node], e0 = rpt[node + 1];
    for (int e = b0; e < e0; e++) {
        int s = colt[e];
        st += xt[s * 32 + lane];
    }

    int b1 = rpi[node], e1 = rpi[node + 1];
    int e = b1;
    for (; e + 32 <= e1; e += 32) {
        int idx = coli[e + lane];
#pragma unroll
        for (int k = 0; k < 32; k++) {
            int s = __shfl_sync(0xffffffffu, idx, k);
            si += xi[s * 32 + lane];
        }
    }
    if (e < e1) {
        int rem = e1 - e;
        int idx = (lane < rem) ? coli[e + lane] : 0;
        for (int k = 0; k < rem; k++) {
            int s = __shfl_sync(0xffffffffu, idx, k);
            si += xi[s * 32 + lane];
        }
    }

    float deg = (float)(e1 - b1);
    float v = st + si / fmaxf(deg, 1.0f) + base[node * 32 + lane];
    v = fmaxf(v, 0.0f);
    if (MODE == 1) v += extra[node * 32 + lane];
    out[node * 32 + lane] = v;
}

// ---------------------------------------------------------------------------
// Aggregation, C=64 (last layer). lane owns channels (2*lane, 2*lane+1) via float2.
// MODE 2: out = relu(agg) + extra    (extra = h @ last_proj)
// ---------------------------------------------------------------------------
__global__ void agg64_kernel(const float* __restrict__ xt, const float* __restrict__ xi,
                             const float* __restrict__ base,
                             const int* __restrict__ rpt, const int* __restrict__ colt,
                             const int* __restrict__ rpi, const int* __restrict__ coli,
                             const float* __restrict__ extra,
                             float* __restrict__ out, int n) {
    int node = blockIdx.x * (blockDim.x >> 5) + (threadIdx.x >> 5);
    if (node >= n) return;
    int lane = threadIdx.x & 31;

    const float2* xt2 = (const float2*)xt;
    const float2* xi2 = (const float2*)xi;

    float2 st = make_float2(0.f, 0.f), si = make_float2(0.f, 0.f);

    int b0 = rpt[node], e0 = rpt[node + 1];
    for (int e = b0; e < e0; e++) {
        int s = colt[e];
        float2 v = xt2[s * 32 + lane];
        st.x += v.x; st.y += v.y;
    }

    int b1 = rpi[node], e1 = rpi[node + 1];
    int e = b1;
    for (; e + 32 <= e1; e += 32) {
        int idx = coli[e + lane];
#pragma unroll
        for (int k = 0; k < 32; k++) {
            int s = __shfl_sync(0xffffffffu, idx, k);
            float2 v = xi2[s * 32 + lane];
            si.x += v.x; si.y += v.y;
        }
    }
    if (e < e1) {
        int rem = e1 - e;
        int idx = (lane < rem) ? coli[e + lane] : 0;
        for (int k = 0; k < rem; k++) {
            int s = __shfl_sync(0xffffffffu, idx, k);
            float2 v = xi2[s * 32 + lane];
            si.x += v.x; si.y += v.y;
        }
    }

    float inv = 1.0f / fmaxf((float)(e1 - b1), 1.0f);
    float2 bs = ((const float2*)base)[node * 32 + lane];
    float2 ex = ((const float2*)extra)[node * 32 + lane];
    float2 r;
    r.x = fmaxf(st.x + si.x * inv + bs.x, 0.0f) + ex.x;
    r.y = fmaxf(st.y + si.y * inv + bs.y, 0.0f) + ex.y;
    ((float2*)out)[node * 32 + lane] = r;
}

// ---------------------------------------------------------------------------
// Launch
// ---------------------------------------------------------------------------
extern "C" void kernel_launch(void* const* d_in, const int* in_sizes, int n_in,
                              void* d_out, int out_size) {
    const float* x        = (const float*)d_in[0];
    const int*   ei_t     = (const int*)d_in[1];
    const int*   ei_i     = (const int*)d_in[2];
    const float* head_Wt  = (const float*)d_in[3];
    const float* head_Wi  = (const float*)d_in[4];
    const float* head_Wr  = (const float*)d_in[5];
    const float* head_b   = (const float*)d_in[6];
    const float* blk_Wt   = (const float*)d_in[7];
    const float* blk_Wi   = (const float*)d_in[8];
    const float* blk_Wr   = (const float*)d_in[9];
    const float* blk_b    = (const float*)d_in[10];
    const float* last_Wt  = (const float*)d_in[11];
    const float* last_Wi  = (const float*)d_in[12];
    const float* last_Wr  = (const float*)d_in[13];
    const float* last_b   = (const float*)d_in[14];
    const float* last_proj= (const float*)d_in[15];

    const int n  = in_sizes[0] / 6;      // 100000
    const int Et = in_sizes[1] / 2;      // 100000
    const int Ei = in_sizes[2] / 2;      // 3200000

    float *xt, *xi, *base, *proj, *h, *h2;
    int *degt, *degi, *rpt, *rpi, *colt, *coli;
    cudaGetSymbolAddress((void**)&xt,   g_xt);
    cudaGetSymbolAddress((void**)&xi,   g_xi);
    cudaGetSymbolAddress((void**)&base, g_base);
    cudaGetSymbolAddress((void**)&proj, g_proj);
    cudaGetSymbolAddress((void**)&h,    g_h);
    cudaGetSymbolAddress((void**)&h2,   g_h2);
    cudaGetSymbolAddress((void**)&degt, g_deg_t);
    cudaGetSymbolAddress((void**)&degi, g_deg_i);
    cudaGetSymbolAddress((void**)&rpt,  g_rpt);
    cudaGetSymbolAddress((void**)&rpi,  g_rpi);
    cudaGetSymbolAddress((void**)&colt, g_col_t);
    cudaGetSymbolAddress((void**)&coli, g_col_i);

    const int T = 256;
    int nodeBlocks = (n * 32 + T - 1) / T;   // warp-per-node grids

    // --- CSR build (both relations) ---
    zero2_kernel<<<(n + T - 1) / T, T>>>(degt, degi, n);
    count_kernel<<<(Et + T - 1) / T, T>>>(ei_t + Et, Et, degt);
    count_kernel<<<(Ei + T - 1) / T, T>>>(ei_i + Ei, Ei, degi);
    scan_kernel<<<1, 1024>>>(degt, rpt, n);
    scan_kernel<<<1, 1024>>>(degi, rpi, n);
    fill_kernel<<<(Et + T - 1) / T, T>>>(ei_t, ei_t + Et, Et, degt, colt);
    fill_kernel<<<(Ei + T - 1) / T, T>>>(ei_i, ei_i + Ei, Ei, degi, coli);

    // --- head: 6 -> 32, relu ---
    transform_kernel<6, 32, false><<<nodeBlocks, T>>>(
        x, head_Wt, head_Wi, head_Wr, head_b, nullptr,
        xt, xi, base, nullptr, n);
    agg32_kernel<0><<<nodeBlocks, T>>>(xt, xi, base, rpt, colt, rpi, coli,
                                       nullptr, h, n);

    // --- 3 residual blocks: 32 -> 32, h = relu(conv(h)) + h ---
    for (int i = 0; i < 3; i++) {
        transform_kernel<32, 32, false><<<nodeBlocks, T>>>(
            h, blk_Wt + i * 32 * 32, blk_Wi + i * 32 * 32,
            blk_Wr + i * 32 * 32, blk_b + i * 32, nullptr,
            xt, xi, base, nullptr, n);
        agg32_kernel<1><<<nodeBlocks, T>>>(xt, xi, base, rpt, colt, rpi, coli,
                                           h, h2, n);
        float* tmp = h; h = h2; h2 = tmp;
    }

    // --- last: 32 -> 64, out = relu(conv(h)) + h @ last_proj ---
    transform_kernel<32, 64, true><<<nodeBlocks, T>>>(
        h, last_Wt, last_Wi, last_Wr, last_b, last_proj,
        xt, xi, base, proj, n);
    agg64_kernel<<<nodeBlocks, T>>>(xt, xi, base, rpt, colt, rpi, coli,
                                    proj, (float*)d_out, n);
}

// round 2
// speedup vs baseline: 1.3913x; 1.3913x over previous
#include <cuda_runtime.h>
#include <cuda_bf16.h>

// ---------------------------------------------------------------------------
// Hetero-GNN (5 hetero_conv layers) over N=100000 nodes.
//   inter relation: 3.2M edges, MEAN aggregation
//   temp  relation: 100k edges, SUM aggregation
// Strategy: per-call CSR build (dst-indexed), transform-then-gather.
// R2: multi-block scan replaces the 144us single-block scan (x2).
// ---------------------------------------------------------------------------

#define N_NODES 100000
#define MAXC 64

// Scratch (device globals; no allocation allowed)
__device__ float g_xt  [N_NODES * MAXC];
__device__ float g_xi  [N_NODES * MAXC];
__device__ float g_base[N_NODES * MAXC];
__device__ float g_proj[N_NODES * MAXC];
__device__ float g_h   [N_NODES * MAXC];
__device__ float g_h2  [N_NODES * MAXC];

__device__ int g_deg_t[N_NODES];        // degree, then reused as fill cursor
__device__ int g_deg_i[N_NODES];
__device__ int g_rpt  [N_NODES + 1];    // CSR row pointers (temp)
__device__ int g_rpi  [N_NODES + 1];    // CSR row pointers (inter)
__device__ int g_bsum_t[1024];
__device__ int g_bsum_i[1024];
__device__ int g_col_t[100000];
__device__ int g_col_i[3200000];

// ---------------------------------------------------------------------------
// CSR build kernels
// ---------------------------------------------------------------------------
__global__ void zero2_kernel(int* __restrict__ a, int* __restrict__ b, int n) {
    int i = blockIdx.x * blockDim.x + threadIdx.x;
    if (i < n) { a[i] = 0; b[i] = 0; }
}

__global__ void count_kernel(const int* __restrict__ dst, int E, int* __restrict__ deg) {
    int i = blockIdx.x * blockDim.x + threadIdx.x;
    if (i < E) atomicAdd(&deg[dst[i]], 1);
}

// --- 3-pass multi-block exclusive scan ---
// P1: per-block (1024-wide tile) exclusive scan of deg -> rowptr; block total -> bsum
__global__ void scan_p1(const int* __restrict__ deg, int* __restrict__ rowptr,
                        int* __restrict__ bsum, int n) {
    __shared__ int sh[1024];
    int i = blockIdx.x * 1024 + threadIdx.x;
    int v = (i < n) ? deg[i] : 0;
    sh[threadIdx.x] = v;
    __syncthreads();
    for (int off = 1; off < 1024; off <<= 1) {
        int t = (threadIdx.x >= off) ? sh[threadIdx.x - off] : 0;
        __syncthreads();
        sh[threadIdx.x] += t;
        __syncthreads();
    }
    if (i < n) rowptr[i] = sh[threadIdx.x] - v;     // exclusive within block
    if (threadIdx.x == 1023) bsum[blockIdx.x] = sh[1023];
}

// P2: single block, exclusive scan of nb block sums in place (nb <= 1024)
__global__ void scan_p2(int* __restrict__ bsum, int nb) {
    __shared__ int sh[1024];
    int v = (threadIdx.x < nb) ? bsum[threadIdx.x] : 0;
    sh[threadIdx.x] = v;
    __syncthreads();
    for (int off = 1; off < 1024; off <<= 1) {
        int t = (threadIdx.x >= off) ? sh[threadIdx.x - off] : 0;
        __syncthreads();
        sh[threadIdx.x] += t;
        __syncthreads();
    }
    if (threadIdx.x < nb) bsum[threadIdx.x] = sh[threadIdx.x] - v;  // exclusive
}

// P3: add block offsets in place, mirror into the fill cursor, set rowptr[n]=E
__global__ void scan_p3(int* __restrict__ rowptr, const int* __restrict__ bsum,
                        int* __restrict__ cursor, int n, int E) {
    int i = blockIdx.x * blockDim.x + threadIdx.x;
    if (i < n) {
        int v = rowptr[i] + bsum[i >> 10];
        rowptr[i] = v;
        cursor[i] = v;
    }
    if (i == 0) rowptr[n] = E;
}

__global__ void fill_kernel(const int* __restrict__ src, const int* __restrict__ dst,
                            int E, int* __restrict__ cursor, int* __restrict__ col) {
    int i = blockIdx.x * blockDim.x + threadIdx.x;
    if (i < E) {
        int d = dst[i];
        int p = atomicAdd(&cursor[d], 1);
        col[p] = src[i];
    }
}

// ---------------------------------------------------------------------------
// Transform: xt = x@Wt, xi = x@Wi, base = x@Wr + b [, proj = x@Wp]
// warp-per-node; lanes own output channels -> coalesced stores.
// ---------------------------------------------------------------------------
template<int CIN, int COUT, bool PROJ>
__global__ void transform_kernel(const float* __restrict__ x,
                                 const float* __restrict__ Wt,
                                 const float* __restrict__ Wi,
                                 const float* __restrict__ Wr,
                                 const float* __restrict__ b,
                                 const float* __restrict__ Wp,
                                 float* __restrict__ xt,
                                 float* __restrict__ xi,
                                 float* __restrict__ base,
                                 float* __restrict__ proj,
                                 int n) {
    __shared__ float sWt[CIN * COUT];
    __shared__ float sWi[CIN * COUT];
    __shared__ float sWr[CIN * COUT];
    __shared__ float sWp[PROJ ? (CIN * COUT) : 1];
    __shared__ float sB[COUT];
    for (int i = threadIdx.x; i < CIN * COUT; i += blockDim.x) {
        sWt[i] = Wt[i]; sWi[i] = Wi[i]; sWr[i] = Wr[i];
        if (PROJ) sWp[i] = Wp[i];
    }
    for (int i = threadIdx.x; i < COUT; i += blockDim.x) sB[i] = b[i];
    __syncthreads();

    int wpb  = blockDim.x >> 5;
    int node = blockIdx.x * wpb + (threadIdx.x >> 5);
    if (node >= n) return;
    int lane = threadIdx.x & 31;

    float xr[CIN];
#pragma unroll
    for (int ci = 0; ci < CIN; ci++) xr[ci] = x[node * CIN + ci];

    constexpr int R = (COUT + 31) / 32;
#pragma unroll
    for (int r = 0; r < R; r++) {
        int co = lane + 32 * r;
        float at = 0.f, ai = 0.f, ar = sB[co], ap = 0.f;
#pragma unroll
        for (int ci = 0; ci < CIN; ci++) {
            float xv = xr[ci];
            at = fmaf(xv, sWt[ci * COUT + co], at);
            ai = fmaf(xv, sWi[ci * COUT + co], ai);
            ar = fmaf(xv, sWr[ci * COUT + co], ar);
            if (PROJ) ap = fmaf(xv, sWp[ci * COUT + co], ap);
        }
        xt[node * COUT + co]   = at;
        xi[node * COUT + co]   = ai;
        base[node * COUT + co] = ar;
        if (PROJ) proj[node * COUT + co] = ap;
    }
}

// ---------------------------------------------------------------------------
// Aggregation, C=32. warp-per-node, lane = channel.
// MODE 0: out = relu(agg)            (head)
// MODE 1: out = relu(agg) + extra    (residual blocks, extra = h_prev)
// ---------------------------------------------------------------------------
template<int MODE>
__global__ void agg32_kernel(const float* __restrict__ xt, const float* __restrict__ xi,
                             const float* __restrict__ base,
                             const int* __restrict__ rpt, const int* __restrict__ colt,
                             const int* __restrict__ rpi, const int* __restrict__ coli,
                             const float* __restrict__ extra,
                             float* __restrict__ out, int n) {
    int node = blockIdx.x * (blockDim.x >> 5) + (threadIdx.x >> 5);
    if (node >= n) return;
    int lane = threadIdx.x & 31;

    float st = 0.f, si = 0.f;

    int b0 = rpt[node], e0 = rpt[node + 1];
    for (int e = b0; e < e0; e++) {
        int s = colt[e];
        st += xt[s * 32 + lane];
    }

    int b1 = rpi[node], e1 = rpi[node + 1];
    int e = b1;
    for (; e + 32 <= e1; e += 32) {
        int idx = coli[e + lane];
#pragma unroll
        for (int k = 0; k < 32; k++) {
            int s = __shfl_sync(0xffffffffu, idx, k);
            si += xi[s * 32 + lane];
        }
    }
    if (e < e1) {
        int rem = e1 - e;
        int idx = (lane < rem) ? coli[e + lane] : 0;
        for (int k = 0; k < rem; k++) {
            int s = __shfl_sync(0xffffffffu, idx, k);
            si += xi[s * 32 + lane];
        }
    }

    float deg = (float)(e1 - b1);
    float v = st + si / fmaxf(deg, 1.0f) + base[node * 32 + lane];
    v = fmaxf(v, 0.0f);
    if (MODE == 1) v += extra[node * 32 + lane];
    out[node * 32 + lane] = v;
}

// ---------------------------------------------------------------------------
// Aggregation, C=64 (last layer). lane owns channels (2*lane, 2*lane+1) via float2.
// out = relu(agg) + extra  (extra = h @ last_proj)
// ---------------------------------------------------------------------------
__global__ void agg64_kernel(const float* __restrict__ xt, const float* __restrict__ xi,
                             const float* __restrict__ base,
                             const int* __restrict__ rpt, const int* __restrict__ colt,
                             const int* __restrict__ rpi, const int* __restrict__ coli,
                             const float* __restrict__ extra,
                             float* __restrict__ out, int n) {
    int node = blockIdx.x * (blockDim.x >> 5) + (threadIdx.x >> 5);
    if (node >= n) return;
    int lane = threadIdx.x & 31;

    const float2* xt2 = (const float2*)xt;
    const float2* xi2 = (const float2*)xi;

    float2 st = make_float2(0.f, 0.f), si = make_float2(0.f, 0.f);

    int b0 = rpt[node], e0 = rpt[node + 1];
    for (int e = b0; e < e0; e++) {
        int s = colt[e];
        float2 v = xt2[s * 32 + lane];
        st.x += v.x; st.y += v.y;
    }

    int b1 = rpi[node], e1 = rpi[node + 1];
    int e = b1;
    for (; e + 32 <= e1; e += 32) {
        int idx = coli[e + lane];
#pragma unroll
        for (int k = 0; k < 32; k++) {
            int s = __shfl_sync(0xffffffffu, idx, k);
            float2 v = xi2[s * 32 + lane];
            si.x += v.x; si.y += v.y;
        }
    }
    if (e < e1) {
        int rem = e1 - e;
        int idx = (lane < rem) ? coli[e + lane] : 0;
        for (int k = 0; k < rem; k++) {
            int s = __shfl_sync(0xffffffffu, idx, k);
            float2 v = xi2[s * 32 + lane];
            si.x += v.x; si.y += v.y;
        }
    }

    float inv = 1.0f / fmaxf((float)(e1 - b1), 1.0f);
    float2 bs = ((const float2*)base)[node * 32 + lane];
    float2 ex = ((const float2*)extra)[node * 32 + lane];
    float2 r;
    r.x = fmaxf(st.x + si.x * inv + bs.x, 0.0f) + ex.x;
    r.y = fmaxf(st.y + si.y * inv + bs.y, 0.0f) + ex.y;
    ((float2*)out)[node * 32 + lane] = r;
}

// ---------------------------------------------------------------------------
// Launch
// ---------------------------------------------------------------------------
extern "C" void kernel_launch(void* const* d_in, const int* in_sizes, int n_in,
                              void* d_out, int out_size) {
    const float* x        = (const float*)d_in[0];
    const int*   ei_t     = (const int*)d_in[1];
    const int*   ei_i     = (const int*)d_in[2];
    const float* head_Wt  = (const float*)d_in[3];
    const float* head_Wi  = (const float*)d_in[4];
    const float* head_Wr  = (const float*)d_in[5];
    const float* head_b   = (const float*)d_in[6];
    const float* blk_Wt   = (const float*)d_in[7];
    const float* blk_Wi   = (const float*)d_in[8];
    const float* blk_Wr   = (const float*)d_in[9];
    const float* blk_b    = (const float*)d_in[10];
    const float* last_Wt  = (const float*)d_in[11];
    const float* last_Wi  = (const float*)d_in[12];
    const float* last_Wr  = (const float*)d_in[13];
    const float* last_b   = (const float*)d_in[14];
    const float* last_proj= (const float*)d_in[15];

    const int n  = in_sizes[0] / 6;      // 100000
    const int Et = in_sizes[1] / 2;      // 100000
    const int Ei = in_sizes[2] / 2;      // 3200000

    float *xt, *xi, *base, *proj, *h, *h2;
    int *degt, *degi, *rpt, *rpi, *colt, *coli, *bst, *bsi;
    cudaGetSymbolAddress((void**)&xt,   g_xt);
    cudaGetSymbolAddress((void**)&xi,   g_xi);
    cudaGetSymbolAddress((void**)&base, g_base);
    cudaGetSymbolAddress((void**)&proj, g_proj);
    cudaGetSymbolAddress((void**)&h,    g_h);
    cudaGetSymbolAddress((void**)&h2,   g_h2);
    cudaGetSymbolAddress((void**)&degt, g_deg_t);
    cudaGetSymbolAddress((void**)&degi, g_deg_i);
    cudaGetSymbolAddress((void**)&rpt,  g_rpt);
    cudaGetSymbolAddress((void**)&rpi,  g_rpi);
    cudaGetSymbolAddress((void**)&bst,  g_bsum_t);
    cudaGetSymbolAddress((void**)&bsi,  g_bsum_i);
    cudaGetSymbolAddress((void**)&colt, g_col_t);
    cudaGetSymbolAddress((void**)&coli, g_col_i);

    const int T = 256;
    int nodeBlocks = (n * 32 + T - 1) / T;   // warp-per-node grids
    int nb = (n + 1023) / 1024;              // scan tiles

    // --- CSR build (both relations) ---
    zero2_kernel<<<(n + T - 1) / T, T>>>(degt, degi, n);
    count_kernel<<<(Et + T - 1) / T, T>>>(ei_t + Et, Et, degt);
    count_kernel<<<(Ei + T - 1) / T, T>>>(ei_i + Ei, Ei, degi);

    scan_p1<<<nb, 1024>>>(degt, rpt, bst, n);
    scan_p1<<<nb, 1024>>>(degi, rpi, bsi, n);
    scan_p2<<<1, 1024>>>(bst, nb);
    scan_p2<<<1, 1024>>>(bsi, nb);
    scan_p3<<<(n + T) / T, T>>>(rpt, bst, degt, n, Et);
    scan_p3<<<(n + T) / T, T>>>(rpi, bsi, degi, n, Ei);

    fill_kernel<<<(Et + T - 1) / T, T>>>(ei_t, ei_t + Et, Et, degt, colt);
    fill_kernel<<<(Ei + T - 1) / T, T>>>(ei_i, ei_i + Ei, Ei, degi, coli);

    // --- head: 6 -> 32, relu ---
    transform_kernel<6, 32, false><<<nodeBlocks, T>>>(
        x, head_Wt, head_Wi, head_Wr, head_b, nullptr,
        xt, xi, base, nullptr, n);
    agg32_kernel<0><<<nodeBlocks, T>>>(xt, xi, base, rpt, colt, rpi, coli,
                                       nullptr, h, n);

    // --- 3 residual blocks: 32 -> 32, h = relu(conv(h)) + h ---
    for (int i = 0; i < 3; i++) {
        transform_kernel<32, 32, false><<<nodeBlocks, T>>>(
            h, blk_Wt + i * 32 * 32, blk_Wi + i * 32 * 32,
            blk_Wr + i * 32 * 32, blk_b + i * 32, nullptr,
            xt, xi, base, nullptr, n);
        agg32_kernel<1><<<nodeBlocks, T>>>(xt, xi, base, rpt, colt, rpi, coli,
                                           h, h2, n);
        float* tmp = h; h = h2; h2 = tmp;
    }

    // --- last: 32 -> 64, out = relu(conv(h)) + h @ last_proj ---
    transform_kernel<32, 64, true><<<nodeBlocks, T>>>(
        h, last_Wt, last_Wi, last_Wr, last_b, last_proj,
        xt, xi, base, proj, n);
    agg64_kernel<<<nodeBlocks, T>>>(xt, xi, base, rpt, colt, rpi, coli,
                                    proj, (float*)d_out, n);
}